// round 14
// baseline (speedup 1.0000x reference)
#include <cuda_runtime.h>

#define NW 1440
#define NH 721
#define NK 24
#define NHW (NH*NW)
#define NP (NHW/2)
#define NPR 720

#define PI_D 3.14159265358979323846

__device__ float g_cos[NH];
__device__ float g_fcor[NH];
__device__ float g_bm[NK];
__device__ float g_db[NK];
__device__ float g_lr[NK];    // 287 * log(bm[k]/bm[k+1])
__device__ float g_rbm[NK];
__device__ float g_cdip[NK];

__device__ __forceinline__ float bif_f(int k) {
    if (k >= NK) return 0.04f;
    double step = (0.04 - 1.0) / 24.0;
    return (float)(1.0 + step * (double)k);
}
__device__ __forceinline__ float bmid_f(int k) {
    return 0.5f * (bif_f(k) + bif_f(k + 1));
}

__global__ void hcbs_setup() {
    int i = blockIdx.x * blockDim.x + threadIdx.x;
    if (i < NH) {
        double colat = (double)i * (PI_D / 720.0);
        float lat = (float)(PI_D / 2.0 - colat);
        g_cos[i]  = fmaxf((float)cos((double)lat), 1e-3f);
        g_fcor[i] = (float)(2.0 * 7.292e-5) * (float)sin((double)lat);
    }
    if (i < NK) {
        float bm = bmid_f(i);
        g_bm[i]  = bm;
        g_db[i]  = bif_f(i + 1) - bif_f(i);
        g_rbm[i] = 1.0f / bm;
        int up = (i == 0) ? 1 : ((i == NK - 1) ? (NK - 1) : (i + 1));
        int dn = (i == 0) ? 0 : (i - 1);
        g_cdip[i] = 1.0f / (bmid_f(up) - bmid_f(dn));
        g_lr[i] = (i < NK - 1) ? (287.0f * logf(bm / bmid_f(i + 1))) : 0.0f;
    }
}

__global__ void __launch_bounds__(128, 5)
hcbs_main(const float* __restrict__ uvp,
          const float* __restrict__ Tp,
          const float* __restrict__ qp,
          const float* __restrict__ psp,
          float* __restrict__ outp)
{
    int p = blockIdx.x * blockDim.x + threadIdx.x;
    if (p >= NP) return;
    int y  = p / NPR;
    int xp = p - y * NPR;
    int x0 = 2 * xp;
    int idx0 = 2 * p;

    const int iW = (x0 == 0)      ? idx0 + (NW - 1) : idx0 - 1;
    const int iE = (x0 == NW - 2) ? idx0 + 2 - NW   : idx0 + 2;
    const int pN = (y == 0)       ? p : p - NPR;
    const int pS = (y == NH - 1)  ? p : p + NPR;

    const float4* uv4 = (const float4*)uvp;
    const float2* uv2 = (const float2*)uvp;
    const float2* T2  = (const float2*)Tp;
    const float2* q2  = (const float2*)qp;
    const float2* ps2 = (const float2*)psp;

    float4* o_duv4 = (float4*)outp;
    float2* o_dT2  = (float2*)(outp + (size_t)2 * NK * NHW);
    float2* o_dq2  = (float2*)(outp + (size_t)3 * NK * NHW);
    float2* o_dps2 = (float2*)(outp + (size_t)4 * NK * NHW);

    const float DT   = (float)(PI_D / 720.0);
    const float hl   = 0.5f / DT;
    const float phs  = (y == 0 || y == NH - 1) ? (1.0f / DT) : (0.5f / DT);
    const float invR = 1.0f / 6371000.0f;

    const float cosc = g_cos[y];
    const float cosN = g_cos[(y == 0) ? 0 : (y - 1)];
    const float cosS = g_cos[(y == NH - 1) ? (NH - 1) : (y + 1)];
    const float fc   = g_fcor[y];
    const float iRc  = invR / cosc;
    const float hx   = hl * iRc;
    const float aN   = cosN * phs * iRc;
    const float aS   = cosS * phs * iRc;
    const float py   = phs * invR;

    float2 psC = ps2[p];
    float2 psN = ps2[pN], psS = ps2[pS];
    float psW = psp[iW], psE = psp[iE];

    float gpsx0 = (psC.y - psW) * hx;
    float gpsx1 = (psE - psC.x) * hx;
    float gpsy0 = -(psS.x - psN.x) * py;
    float gpsy1 = -(psS.y - psN.y) * py;
    float ips0 = 1.0f / psC.x, ips1 = 1.0f / psC.y;

    // ---------------- sweep 1: dps/dt ----------------
    float dps0 = 0.0f, dps1 = 0.0f;
    #pragma unroll 4
    for (int k = 0; k < NK; k++) {
        int b4 = k * NP;
        int b2 = k * NHW;
        float4 c  = uv4[b4 + p];
        float4 n4 = uv4[b4 + pN];
        float4 s4 = uv4[b4 + pS];
        float uW = uv2[b2 + iW].x;
        float uE = uv2[b2 + iE].x;
        float divg0 = (c.z - uW) * hx - (s4.y * aS - n4.y * aN);
        float divg1 = (uE - c.x) * hx - (s4.w * aS - n4.w * aN);
        float vg0 = c.x * gpsx0 + c.y * gpsy0;
        float vg1 = c.z * gpsx1 + c.w * gpsy1;
        float db = g_db[k];
        dps0 -= db * (psC.x * divg0 + vg0);
        dps1 -= db * (psC.y * divg1 + vg1);
    }
    __stcs(&o_dps2[p], make_float2(dps0, dps1));

    // ---------------- sweep 2: level tendencies ----------------
    float Ch0 = 0.0f, Ch1 = 0.0f;
    float gpx0 = 0.0f, gpy0 = 0.0f, gpx1 = 0.0f, gpy1 = 0.0f;
    float4 cU = uv4[p];
    float2 cT = T2[p], cQ = q2[p];
    float4 pU = cU;
    float2 pT = cT, pQ = cQ;
    const float RCP = 287.0f / 1004.0f;

    #pragma unroll 2
    for (int k = 0; k < NK; k++) {
        int b4 = k * NP;
        int b2 = k * NHW;
        int ku = (k + 1 < NK) ? (k + 1) : k;

        float4 n4 = uv4[b4 + pN];
        float4 s4 = uv4[b4 + pS];
        float2 w2 = uv2[b2 + iW];
        float2 e2 = uv2[b2 + iE];
        float2 TN = T2[b4 + pN], TS = T2[b4 + pS];
        float  TW = Tp[b2 + iW], TE = Tp[b2 + iE];
        float2 qN = q2[b4 + pN], qS = q2[b4 + pS];
        float  qW = qp[b2 + iW], qE = qp[b2 + iE];
        float4 uU = uv4[ku * NP + p];
        float2 uT = T2[ku * NP + p];
        float2 uQ = q2[ku * NP + p];

        float bm = g_bm[k], db = g_db[k];

        float zeta0 = (cU.w - w2.y) * hx + (s4.x * aS - n4.x * aN);
        float divg0 = (cU.z - w2.x) * hx - (s4.y * aS - n4.y * aN);
        float zeta1 = (e2.y - cU.y) * hx + (s4.z * aS - n4.z * aN);
        float divg1 = (e2.x - cU.x) * hx - (s4.w * aS - n4.w * aN);

        float keW  = 0.5f * (w2.x * w2.x + w2.y * w2.y);
        float keE  = 0.5f * (e2.x * e2.x + e2.y * e2.y);
        float ke0  = 0.5f * (cU.x * cU.x + cU.y * cU.y);
        float ke1  = 0.5f * (cU.z * cU.z + cU.w * cU.w);
        float keN0 = 0.5f * (n4.x * n4.x + n4.y * n4.y);
        float keN1 = 0.5f * (n4.z * n4.z + n4.w * n4.w);
        float keS0 = 0.5f * (s4.x * s4.x + s4.y * s4.y);
        float keS1 = 0.5f * (s4.z * s4.z + s4.w * s4.w);

        float gkx0 = (ke1 - keW) * hx, gkx1 = (keE - ke0) * hx;
        float gky0 = -(keS0 - keN0) * py, gky1 = -(keS1 - keN1) * py;
        float gTx0 = (cT.y - TW) * hx, gTx1 = (TE - cT.x) * hx;
        float gTy0 = -(TS.x - TN.x) * py, gTy1 = -(TS.y - TN.y) * py;
        float gqx0 = (cQ.y - qW) * hx, gqx1 = (qE - cQ.x) * hx;
        float gqy0 = -(qS.x - qN.x) * py, gqy1 = -(qS.y - qN.y) * py;

        float vg0 = cU.x * gpsx0 + cU.y * gpsy0;
        float vg1 = cU.z * gpsx1 + cU.w * gpsy1;
        float Cn0 = Ch0 - (db * (dps0 + psC.x * divg0 + vg0));
        float Cn1 = Ch1 - (db * (dps1 + psC.y * divg1 + vg1));
        float Cm0 = 0.5f * (Ch0 + Cn0);
        float Cm1 = 0.5f * (Ch1 + Cn1);
        float om0 = bm * (dps0 + vg0) + Cm0;
        float om1 = bm * (dps1 + vg1) + Cm1;

        float cd0 = g_cdip[k] * ips0;
        float cd1 = g_cdip[k] * ips1;
        float ddpu0 = (uU.x - pU.x) * cd0, ddpv0 = (uU.y - pU.y) * cd0;
        float ddpu1 = (uU.z - pU.z) * cd1, ddpv1 = (uU.w - pU.w) * cd1;
        float ddpT0 = (uT.x - pT.x) * cd0, ddpT1 = (uT.y - pT.y) * cd1;
        float ddpq0 = (uQ.x - pQ.x) * cd0, ddpq1 = (uQ.y - pQ.y) * cd1;

        float av0 = zeta0 + fc, av1 = zeta1 + fc;
        float pgf0 = 287.0f * cT.x * ips0;
        float pgf1 = 287.0f * cT.y * ips1;
        float orb = g_rbm[k];

        float du0 =  av0 * cU.y - (gkx0 + gpx0) - pgf0 * gpsx0 - Cm0 * ddpu0;
        float dv0 = -av0 * cU.x - (gky0 + gpy0) - pgf0 * gpsy0 - Cm0 * ddpv0;
        float du1 =  av1 * cU.w - (gkx1 + gpx1) - pgf1 * gpsx1 - Cm1 * ddpu1;
        float dv1 = -av1 * cU.z - (gky1 + gpy1) - pgf1 * gpsy1 - Cm1 * ddpv1;
        float dT0 = -(cU.x * gTx0 + cU.y * gTy0) - Cm0 * ddpT0
                    + RCP * cT.x * om0 * (ips0 * orb);
        float dT1 = -(cU.z * gTx1 + cU.w * gTy1) - Cm1 * ddpT1
                    + RCP * cT.y * om1 * (ips1 * orb);
        float dq0 = -(cU.x * gqx0 + cU.y * gqy0) - Cm0 * ddpq0;
        float dq1 = -(cU.z * gqx1 + cU.w * gqy1) - Cm1 * ddpq1;

        __stcs(&o_duv4[b4 + p], make_float4(du0, dv0, du1, dv1));
        __stcs(&o_dT2[b4 + p],  make_float2(dT0, dT1));
        __stcs(&o_dq2[b4 + p],  make_float2(dq0, dq1));

        float lrr = g_lr[k];
        gpx0 += lrr * gTx0; gpy0 += lrr * gTy0;
        gpx1 += lrr * gTx1; gpy1 += lrr * gTy1;

        Ch0 = Cn0; Ch1 = Cn1;
        pU = cU; pT = cT; pQ = cQ;
        cU = uU; cT = uT; cQ = uQ;
    }
}

extern "C" void kernel_launch(void* const* d_in, const int* in_sizes, int n_in,
                              void* d_out, int out_size) {
    const float* uv = nullptr;
    const float* T  = nullptr;
    const float* q  = nullptr;
    const float* ps = nullptr;
    for (int i = 0; i < n_in; i++) {
        long long sz = in_sizes[i];
        if (sz == 2LL * NK * NHW)      uv = (const float*)d_in[i];
        else if (sz == (long long)NHW) ps = (const float*)d_in[i];
        else if (sz == (long long)NK * NHW) {
            if (!T) T = (const float*)d_in[i];
            else    q = (const float*)d_in[i];
        }
    }
    hcbs_setup<<<6, 128>>>();
    int threads = 128;
    int blocks  = (NP + threads - 1) / threads;
    hcbs_main<<<blocks, threads>>>(uv, T, q, ps, (float*)d_out);
}

// round 16
// speedup vs baseline: 1.3078x; 1.3078x over previous
#include <cuda_runtime.h>

#define NW 1440
#define NH 721
#define NK 24
#define NHW (NH*NW)
#define NP (NHW/2)
#define NPR 720

#define PI_D 3.14159265358979323846

__device__ float g_cos[NH];
__device__ float g_fcor[NH];
__device__ float g_bm[NK];
__device__ float g_db[NK];
__device__ float g_lr[NK];    // 287 * log(bm[k]/bm[k+1])
__device__ float g_rbm[NK];
__device__ float g_cdip[NK];

__device__ __forceinline__ float bif_f(int k) {
    if (k >= NK) return 0.04f;
    double step = (0.04 - 1.0) / 24.0;
    return (float)(1.0 + step * (double)k);
}
__device__ __forceinline__ float bmid_f(int k) {
    return 0.5f * (bif_f(k) + bif_f(k + 1));
}

__global__ void hcbs_setup() {
    int i = blockIdx.x * blockDim.x + threadIdx.x;
    if (i < NH) {
        double colat = (double)i * (PI_D / 720.0);
        float lat = (float)(PI_D / 2.0 - colat);
        g_cos[i]  = fmaxf((float)cos((double)lat), 1e-3f);
        g_fcor[i] = (float)(2.0 * 7.292e-5) * (float)sin((double)lat);
    }
    if (i < NK) {
        float bm = bmid_f(i);
        g_bm[i]  = bm;
        g_db[i]  = bif_f(i + 1) - bif_f(i);
        g_rbm[i] = 1.0f / bm;
        int up = (i == 0) ? 1 : ((i == NK - 1) ? (NK - 1) : (i + 1));
        int dn = (i == 0) ? 0 : (i - 1);
        g_cdip[i] = 1.0f / (bmid_f(up) - bmid_f(dn));
        g_lr[i] = (i < NK - 1) ? (287.0f * logf(bm / bmid_f(i + 1))) : 0.0f;
    }
}

__global__ void __launch_bounds__(128, 6)
hcbs_main(const float* __restrict__ uvp,
          const float* __restrict__ Tp,
          const float* __restrict__ qp,
          const float* __restrict__ psp,
          float* __restrict__ outp)
{
    int p = blockIdx.x * blockDim.x + threadIdx.x;
    if (p >= NP) return;
    int y  = p / NPR;
    int xp = p - y * NPR;
    int x0 = 2 * xp;
    int idx0 = 2 * p;

    const int iW = (x0 == 0)      ? idx0 + (NW - 1) : idx0 - 1;
    const int iE = (x0 == NW - 2) ? idx0 + 2 - NW   : idx0 + 2;
    const int pN = (y == 0)       ? p : p - NPR;
    const int pS = (y == NH - 1)  ? p : p + NPR;

    const float4* uv4 = (const float4*)uvp;
    const float2* uv2 = (const float2*)uvp;
    const float2* T2  = (const float2*)Tp;
    const float2* q2  = (const float2*)qp;
    const float2* ps2 = (const float2*)psp;

    float4* o_duv4 = (float4*)outp;
    float2* o_dT2  = (float2*)(outp + (size_t)2 * NK * NHW);
    float2* o_dq2  = (float2*)(outp + (size_t)3 * NK * NHW);
    float2* o_dps2 = (float2*)(outp + (size_t)4 * NK * NHW);

    const float DT   = (float)(PI_D / 720.0);
    const float hl   = 0.5f / DT;
    const float phs  = (y == 0 || y == NH - 1) ? (1.0f / DT) : (0.5f / DT);
    const float invR = 1.0f / 6371000.0f;

    const float cosc = g_cos[y];
    const float cosN = g_cos[(y == 0) ? 0 : (y - 1)];
    const float cosS = g_cos[(y == NH - 1) ? (NH - 1) : (y + 1)];
    const float fc   = g_fcor[y];
    const float iRc  = invR / cosc;
    const float hx   = hl * iRc;
    const float aN   = cosN * phs * iRc;
    const float aS   = cosS * phs * iRc;
    const float py   = phs * invR;

    float2 psC = ps2[p];
    float2 psN = ps2[pN], psS = ps2[pS];
    float psW = psp[iW], psE = psp[iE];

    float gpsx0 = (psC.y - psW) * hx;
    float gpsx1 = (psE - psC.x) * hx;
    float gpsy0 = -(psS.x - psN.x) * py;
    float gpsy1 = -(psS.y - psN.y) * py;
    float ips0 = 1.0f / psC.x, ips1 = 1.0f / psC.y;

    // ---------------- sweep 1: dps/dt ----------------
    float dps0 = 0.0f, dps1 = 0.0f;
    #pragma unroll 4
    for (int k = 0; k < NK; k++) {
        int b4 = k * NP;
        int b2 = k * NHW;
        float4 c  = uv4[b4 + p];
        float4 n4 = uv4[b4 + pN];
        float4 s4 = uv4[b4 + pS];
        float uW = uv2[b2 + iW].x;
        float uE = uv2[b2 + iE].x;
        float divg0 = (c.z - uW) * hx - (s4.y * aS - n4.y * aN);
        float divg1 = (uE - c.x) * hx - (s4.w * aS - n4.w * aN);
        float vg0 = c.x * gpsx0 + c.y * gpsy0;
        float vg1 = c.z * gpsx1 + c.w * gpsy1;
        float db = g_db[k];
        dps0 -= db * (psC.x * divg0 + vg0);
        dps1 -= db * (psC.y * divg1 + vg1);
    }
    __stcs(&o_dps2[p], make_float2(dps0, dps1));

    // ---------------- sweep 2: level tendencies ----------------
    float Ch0 = 0.0f, Ch1 = 0.0f;
    float gpx0 = 0.0f, gpy0 = 0.0f, gpx1 = 0.0f, gpy1 = 0.0f;
    float4 cU = uv4[p];
    float2 cT = T2[p], cQ = q2[p];
    float4 pU = cU;
    float2 pT = cT, pQ = cQ;
    const float RCP = 287.0f / 1004.0f;

    #pragma unroll 1
    for (int k = 0; k < NK; k++) {
        int b4 = k * NP;
        int b2 = k * NHW;
        int ku = (k + 1 < NK) ? (k + 1) : k;

        float4 n4 = uv4[b4 + pN];
        float4 s4 = uv4[b4 + pS];
        float2 w2 = uv2[b2 + iW];
        float2 e2 = uv2[b2 + iE];
        float2 TN = T2[b4 + pN], TS = T2[b4 + pS];
        float  TW = Tp[b2 + iW], TE = Tp[b2 + iE];
        float2 qN = q2[b4 + pN], qS = q2[b4 + pS];
        float  qW = qp[b2 + iW], qE = qp[b2 + iE];
        float4 uU = uv4[ku * NP + p];
        float2 uT = T2[ku * NP + p];
        float2 uQ = q2[ku * NP + p];

        float bm = g_bm[k], db = g_db[k];

        float zeta0 = (cU.w - w2.y) * hx + (s4.x * aS - n4.x * aN);
        float divg0 = (cU.z - w2.x) * hx - (s4.y * aS - n4.y * aN);
        float zeta1 = (e2.y - cU.y) * hx + (s4.z * aS - n4.z * aN);
        float divg1 = (e2.x - cU.x) * hx - (s4.w * aS - n4.w * aN);

        float keW  = 0.5f * (w2.x * w2.x + w2.y * w2.y);
        float keE  = 0.5f * (e2.x * e2.x + e2.y * e2.y);
        float ke0  = 0.5f * (cU.x * cU.x + cU.y * cU.y);
        float ke1  = 0.5f * (cU.z * cU.z + cU.w * cU.w);
        float keN0 = 0.5f * (n4.x * n4.x + n4.y * n4.y);
        float keN1 = 0.5f * (n4.z * n4.z + n4.w * n4.w);
        float keS0 = 0.5f * (s4.x * s4.x + s4.y * s4.y);
        float keS1 = 0.5f * (s4.z * s4.z + s4.w * s4.w);

        float gkx0 = (ke1 - keW) * hx, gkx1 = (keE - ke0) * hx;
        float gky0 = -(keS0 - keN0) * py, gky1 = -(keS1 - keN1) * py;
        float gTx0 = (cT.y - TW) * hx, gTx1 = (TE - cT.x) * hx;
        float gTy0 = -(TS.x - TN.x) * py, gTy1 = -(TS.y - TN.y) * py;
        float gqx0 = (cQ.y - qW) * hx, gqx1 = (qE - cQ.x) * hx;
        float gqy0 = -(qS.x - qN.x) * py, gqy1 = -(qS.y - qN.y) * py;

        float vg0 = cU.x * gpsx0 + cU.y * gpsy0;
        float vg1 = cU.z * gpsx1 + cU.w * gpsy1;
        float Cn0 = Ch0 - (db * (dps0 + psC.x * divg0 + vg0));
        float Cn1 = Ch1 - (db * (dps1 + psC.y * divg1 + vg1));
        float Cm0 = 0.5f * (Ch0 + Cn0);
        float Cm1 = 0.5f * (Ch1 + Cn1);
        float om0 = bm * (dps0 + vg0) + Cm0;
        float om1 = bm * (dps1 + vg1) + Cm1;

        float cd0 = g_cdip[k] * ips0;
        float cd1 = g_cdip[k] * ips1;
        float ddpu0 = (uU.x - pU.x) * cd0, ddpv0 = (uU.y - pU.y) * cd0;
        float ddpu1 = (uU.z - pU.z) * cd1, ddpv1 = (uU.w - pU.w) * cd1;
        float ddpT0 = (uT.x - pT.x) * cd0, ddpT1 = (uT.y - pT.y) * cd1;
        float ddpq0 = (uQ.x - pQ.x) * cd0, ddpq1 = (uQ.y - pQ.y) * cd1;

        float av0 = zeta0 + fc, av1 = zeta1 + fc;
        float pgf0 = 287.0f * cT.x * ips0;
        float pgf1 = 287.0f * cT.y * ips1;
        float orb = g_rbm[k];

        float du0 =  av0 * cU.y - (gkx0 + gpx0) - pgf0 * gpsx0 - Cm0 * ddpu0;
        float dv0 = -av0 * cU.x - (gky0 + gpy0) - pgf0 * gpsy0 - Cm0 * ddpv0;
        float du1 =  av1 * cU.w - (gkx1 + gpx1) - pgf1 * gpsx1 - Cm1 * ddpu1;
        float dv1 = -av1 * cU.z - (gky1 + gpy1) - pgf1 * gpsy1 - Cm1 * ddpv1;
        float dT0 = -(cU.x * gTx0 + cU.y * gTy0) - Cm0 * ddpT0
                    + RCP * cT.x * om0 * (ips0 * orb);
        float dT1 = -(cU.z * gTx1 + cU.w * gTy1) - Cm1 * ddpT1
                    + RCP * cT.y * om1 * (ips1 * orb);
        float dq0 = -(cU.x * gqx0 + cU.y * gqy0) - Cm0 * ddpq0;
        float dq1 = -(cU.z * gqx1 + cU.w * gqy1) - Cm1 * ddpq1;

        __stcs(&o_duv4[b4 + p], make_float4(du0, dv0, du1, dv1));
        __stcs(&o_dT2[b4 + p],  make_float2(dT0, dT1));
        __stcs(&o_dq2[b4 + p],  make_float2(dq0, dq1));

        float lrr = g_lr[k];
        gpx0 += lrr * gTx0; gpy0 += lrr * gTy0;
        gpx1 += lrr * gTx1; gpy1 += lrr * gTy1;

        Ch0 = Cn0; Ch1 = Cn1;
        pU = cU; pT = cT; pQ = cQ;
        cU = uU; cT = uT; cQ = uQ;
    }
}

extern "C" void kernel_launch(void* const* d_in, const int* in_sizes, int n_in,
                              void* d_out, int out_size) {
    const float* uv = nullptr;
    const float* T  = nullptr;
    const float* q  = nullptr;
    const float* ps = nullptr;
    for (int i = 0; i < n_in; i++) {
        long long sz = in_sizes[i];
        if (sz == 2LL * NK * NHW)      uv = (const float*)d_in[i];
        else if (sz == (long long)NHW) ps = (const float*)d_in[i];
        else if (sz == (long long)NK * NHW) {
            if (!T) T = (const float*)d_in[i];
            else    q = (const float*)d_in[i];
        }
    }
    hcbs_setup<<<6, 128>>>();
    int threads = 128;
    int blocks  = (NP + threads - 1) / threads;
    hcbs_main<<<blocks, threads>>>(uv, T, q, ps, (float*)d_out);
}

// round 17
// speedup vs baseline: 1.4231x; 1.0882x over previous
#include <cuda_runtime.h>

#define NW 1440
#define NH 721
#define NK 24
#define NHW (NH*NW)
#define NP (NHW/2)
#define NPR (NW/2)

#define PI_D 3.14159265358979323846

__device__ float g_cos[NH];
__device__ float g_fcor[NH];
__device__ float g_bm[NK];
__device__ float g_db[NK];
__device__ float g_lr[NK];
__device__ float g_rbm[NK];
__device__ float g_cdip[NK];
__device__ float g_UV[2 * NHW];   // column sums (U,V) per point

__device__ __forceinline__ float bif_f(int k) {
    if (k >= NK) return 0.04f;
    double step = (0.04 - 1.0) / 24.0;
    return (float)(1.0 + step * (double)k);
}
__device__ __forceinline__ float bmid_f(int k) {
    return 0.5f * (bif_f(k) + bif_f(k + 1));
}

__global__ void hcbs_setup() {
    int i = blockIdx.x * blockDim.x + threadIdx.x;
    if (i < NH) {
        double colat = (double)i * (PI_D / 720.0);
        float lat = (float)(PI_D / 2.0 - colat);
        g_cos[i]  = fmaxf((float)cos((double)lat), 1e-3f);
        g_fcor[i] = (float)(2.0 * 7.292e-5) * (float)sin((double)lat);
    }
    if (i < NK) {
        float bm = bmid_f(i);
        g_bm[i]  = bm;
        g_db[i]  = bif_f(i + 1) - bif_f(i);
        g_rbm[i] = 1.0f / bm;
        int up = (i == 0) ? 1 : ((i == NK - 1) ? (NK - 1) : (i + 1));
        int dn = (i == 0) ? 0 : (i - 1);
        g_cdip[i] = 1.0f / (bmid_f(up) - bmid_f(dn));
        g_lr[i] = (i < NK - 1) ? logf(bm / bmid_f(i + 1)) : 0.0f;
    }
}

// ---- pure-streaming vertical column sum: U = sum db*u, V = sum db*v ----
__global__ void __launch_bounds__(256)
hcbs_colsum(const float4* __restrict__ uv4)
{
    int p = blockIdx.x * blockDim.x + threadIdx.x;
    if (p >= NP) return;
    float U0 = 0.f, V0 = 0.f, U1 = 0.f, V1 = 0.f;
    #pragma unroll
    for (int k = 0; k < NK; k++) {
        float4 c = uv4[(size_t)k * NP + p];
        float db = g_db[k];
        U0 += db * c.x; V0 += db * c.y;
        U1 += db * c.z; V1 += db * c.w;
    }
    ((float4*)g_UV)[p] = make_float4(U0, V0, U1, V1);
}

__global__ void __launch_bounds__(128, 5)
hcbs_main(const float* __restrict__ uvp,
          const float* __restrict__ Tp,
          const float* __restrict__ qp,
          const float* __restrict__ psp,
          float* __restrict__ outp)
{
    int praw = blockIdx.x * blockDim.x + threadIdx.x;
    bool wr = (praw < NP);
    int p = wr ? praw : (NP - 1);
    int lane = threadIdx.x & 31;

    int y  = p / NPR;
    int xp = p - y * NPR;
    int x0 = 2 * xp;
    int idx0 = 2 * p;

    int iW = (x0 == 0)      ? idx0 + (NW - 1) : idx0 - 1;
    int iE = (x0 == NW - 2) ? idx0 + 2 - NW   : idx0 + 2;
    int pN = (y == 0)       ? p : p - NPR;
    int pS = (y == NH - 1)  ? p : p + NPR;

    bool loadW = (lane == 0)  || (xp == 0);
    bool loadE = (lane == 31) || (xp == NPR - 1);

    const float4* uv4 = (const float4*)uvp;
    const float2* uv2 = (const float2*)uvp;
    const float2* T2  = (const float2*)Tp;
    const float2* q2  = (const float2*)qp;
    const float2* ps2 = (const float2*)psp;
    const float4* UV4 = (const float4*)g_UV;
    const float2* UV2 = (const float2*)g_UV;

    float4* o_duv4 = (float4*)outp;
    float2* o_dT2  = (float2*)(outp + (size_t)2 * NK * NHW);
    float2* o_dq2  = (float2*)(outp + (size_t)3 * NK * NHW);
    float2* o_dps2 = (float2*)(outp + (size_t)4 * NK * NHW);

    const float DT   = (float)(PI_D / 720.0);
    const float hl   = 0.5f / DT;
    float phs = (y == 0 || y == NH - 1) ? (1.0f / DT) : (0.5f / DT);
    const float invR = 1.0f / 6371000.0f;

    float cosc = g_cos[y];
    float cosN = g_cos[(y == 0) ? 0 : (y - 1)];
    float cosS = g_cos[(y == NH - 1) ? (NH - 1) : (y + 1)];
    float fc   = g_fcor[y];
    float iRc  = invR / cosc;
    float hx   = hl * iRc;
    float aN   = cosN * phs * iRc;
    float aS   = cosS * phs * iRc;
    float py   = phs * invR;

    float2 psC = ps2[p];
    float2 psN = ps2[pN], psS = ps2[pS];
    float psW = psp[iW], psE = psp[iE];

    float gpsx0 = (psC.y - psW) * hx;
    float gpsx1 = (psE - psC.x) * hx;
    float gpsy0 = -(psS.x - psN.x) * py;
    float gpsy1 = -(psS.y - psN.y) * py;
    float ips0 = 1.0f / psC.x, ips1 = 1.0f / psC.y;

    // ---- dps from precomputed column sums ----
    float4 Uc = UV4[p], Un = UV4[pN], Us = UV4[pS];
    float2 Uw = UV2[iW], Ue = UV2[iE];
    float divU0 = (Uc.z - Uw.x) * hx - (Us.y * aS - Un.y * aN);
    float divU1 = (Ue.x - Uc.x) * hx - (Us.w * aS - Un.w * aN);
    float dps0 = -(psC.x * divU0 + Uc.x * gpsx0 + Uc.y * gpsy0);
    float dps1 = -(psC.y * divU1 + Uc.z * gpsx1 + Uc.w * gpsy1);
    if (wr) o_dps2[p] = make_float2(dps0, dps1);

    // ---- level sweep ----
    float Ch0 = 0.0f, Ch1 = 0.0f;
    float gpx0 = 0.0f, gpy0 = 0.0f, gpx1 = 0.0f, gpy1 = 0.0f;
    float4 cU = uv4[p];
    float2 cT = T2[p], cQ = q2[p];
    float4 pU = cU;
    float2 pT = cT, pQ = cQ;
    const float RCP = 287.0f / 1004.0f;
    const unsigned FULL = 0xffffffffu;

    #pragma unroll 1
    for (int k = 0; k < NK; k++) {
        int b4 = k * NP;
        int b2 = k * NHW;
        int ku = (k + 1 < NK) ? (k + 1) : k;

        float4 n4 = uv4[b4 + pN];
        float4 s4 = uv4[b4 + pS];
        float2 TN = T2[b4 + pN], TS = T2[b4 + pS];
        float2 qN = q2[b4 + pN], qS = q2[b4 + pS];
        float4 uU = uv4[ku * NP + p];
        float2 uT = T2[ku * NP + p];
        float2 uQ = q2[ku * NP + p];

        // E/W neighbors from adjacent lanes' registers
        float wu = __shfl_up_sync(FULL, cU.z, 1);
        float wv = __shfl_up_sync(FULL, cU.w, 1);
        float eu = __shfl_down_sync(FULL, cU.x, 1);
        float ev = __shfl_down_sync(FULL, cU.y, 1);
        float TW = __shfl_up_sync(FULL, cT.y, 1);
        float TE = __shfl_down_sync(FULL, cT.x, 1);
        float qW = __shfl_up_sync(FULL, cQ.y, 1);
        float qE = __shfl_down_sync(FULL, cQ.x, 1);
        if (loadW) {
            float2 t = uv2[b2 + iW];
            wu = t.x; wv = t.y;
            TW = Tp[b2 + iW]; qW = qp[b2 + iW];
        }
        if (loadE) {
            float2 t = uv2[b2 + iE];
            eu = t.x; ev = t.y;
            TE = Tp[b2 + iE]; qE = qp[b2 + iE];
        }

        float bm = g_bm[k], db = g_db[k];

        float zeta0 = (cU.w - wv) * hx + (s4.x * aS - n4.x * aN);
        float divg0 = (cU.z - wu) * hx - (s4.y * aS - n4.y * aN);
        float zeta1 = (ev - cU.y) * hx + (s4.z * aS - n4.z * aN);
        float divg1 = (eu - cU.x) * hx - (s4.w * aS - n4.w * aN);

        float keW  = 0.5f * (wu * wu + wv * wv);
        float keE  = 0.5f * (eu * eu + ev * ev);
        float ke0  = 0.5f * (cU.x * cU.x + cU.y * cU.y);
        float ke1  = 0.5f * (cU.z * cU.z + cU.w * cU.w);
        float keN0 = 0.5f * (n4.x * n4.x + n4.y * n4.y);
        float keN1 = 0.5f * (n4.z * n4.z + n4.w * n4.w);
        float keS0 = 0.5f * (s4.x * s4.x + s4.y * s4.y);
        float keS1 = 0.5f * (s4.z * s4.z + s4.w * s4.w);

        float gkx0 = (ke1 - keW) * hx, gkx1 = (keE - ke0) * hx;
        float gky0 = -(keS0 - keN0) * py, gky1 = -(keS1 - keN1) * py;
        float gTx0 = (cT.y - TW) * hx, gTx1 = (TE - cT.x) * hx;
        float gTy0 = -(TS.x - TN.x) * py, gTy1 = -(TS.y - TN.y) * py;
        float gqx0 = (cQ.y - qW) * hx, gqx1 = (qE - cQ.x) * hx;
        float gqy0 = -(qS.x - qN.x) * py, gqy1 = -(qS.y - qN.y) * py;

        float vg0 = cU.x * gpsx0 + cU.y * gpsy0;
        float vg1 = cU.z * gpsx1 + cU.w * gpsy1;
        float Cn0 = Ch0 - (db * (dps0 + psC.x * divg0 + vg0));
        float Cn1 = Ch1 - (db * (dps1 + psC.y * divg1 + vg1));
        float Cm0 = 0.5f * (Ch0 + Cn0);
        float Cm1 = 0.5f * (Ch1 + Cn1);
        float om0 = bm * (dps0 + vg0) + Cm0;
        float om1 = bm * (dps1 + vg1) + Cm1;

        float cd0 = g_cdip[k] * ips0;
        float cd1 = g_cdip[k] * ips1;
        float ddpu0 = (uU.x - pU.x) * cd0, ddpv0 = (uU.y - pU.y) * cd0;
        float ddpu1 = (uU.z - pU.z) * cd1, ddpv1 = (uU.w - pU.w) * cd1;
        float ddpT0 = (uT.x - pT.x) * cd0, ddpT1 = (uT.y - pT.y) * cd1;
        float ddpq0 = (uQ.x - pQ.x) * cd0, ddpq1 = (uQ.y - pQ.y) * cd1;

        float av0 = zeta0 + fc, av1 = zeta1 + fc;
        float pgf0 = 287.0f * cT.x * ips0;
        float pgf1 = 287.0f * cT.y * ips1;
        float orb = g_rbm[k];

        float du0 =  av0 * cU.y - (gkx0 + gpx0) - pgf0 * gpsx0 - Cm0 * ddpu0;
        float dv0 = -av0 * cU.x - (gky0 + gpy0) - pgf0 * gpsy0 - Cm0 * ddpv0;
        float du1 =  av1 * cU.w - (gkx1 + gpx1) - pgf1 * gpsx1 - Cm1 * ddpu1;
        float dv1 = -av1 * cU.z - (gky1 + gpy1) - pgf1 * gpsy1 - Cm1 * ddpv1;
        float dT0 = -(cU.x * gTx0 + cU.y * gTy0) - Cm0 * ddpT0
                    + RCP * cT.x * om0 * (ips0 * orb);
        float dT1 = -(cU.z * gTx1 + cU.w * gTy1) - Cm1 * ddpT1
                    + RCP * cT.y * om1 * (ips1 * orb);
        float dq0 = -(cU.x * gqx0 + cU.y * gqy0) - Cm0 * ddpq0;
        float dq1 = -(cU.z * gqx1 + cU.w * gqy1) - Cm1 * ddpq1;

        if (wr) {
            o_duv4[b4 + p] = make_float4(du0, dv0, du1, dv1);
            o_dT2[b4 + p]  = make_float2(dT0, dT1);
            o_dq2[b4 + p]  = make_float2(dq0, dq1);
        }

        float lrr = 287.0f * g_lr[k];
        gpx0 += lrr * gTx0; gpy0 += lrr * gTy0;
        gpx1 += lrr * gTx1; gpy1 += lrr * gTy1;

        Ch0 = Cn0; Ch1 = Cn1;
        pU = cU; pT = cT; pQ = cQ;
        cU = uU; cT = uT; cQ = uQ;
    }
}

extern "C" void kernel_launch(void* const* d_in, const int* in_sizes, int n_in,
                              void* d_out, int out_size) {
    const float* uv = nullptr;
    const float* T  = nullptr;
    const float* q  = nullptr;
    const float* ps = nullptr;
    for (int i = 0; i < n_in; i++) {
        long long sz = in_sizes[i];
        if (sz == 2LL * NK * NHW)      uv = (const float*)d_in[i];
        else if (sz == (long long)NHW) ps = (const float*)d_in[i];
        else if (sz == (long long)NK * NHW) {
            if (!T) T = (const float*)d_in[i];
            else    q = (const float*)d_in[i];
        }
    }
    hcbs_setup<<<6, 128>>>();
    hcbs_colsum<<<(NP + 255) / 256, 256>>>((const float4*)uv);
    int threads = 128;
    int blocks  = (NP + threads - 1) / threads;
    hcbs_main<<<blocks, threads>>>(uv, T, q, ps, (float*)d_out);
}